// round 2
// baseline (speedup 1.0000x reference)
#include <cuda_runtime.h>
#include <math.h>

#define NN 4096
#define DD 128
#define TAU_INV 5.0f
#define EPSV 1e-8f
#define QIDX 3276              // floor(0.8 * (NN-1))
#define TOPK (NN - QIDX)       // 820
#define NBINS 1024
#define LCAP 1024

// Scratch (static __device__ arrays, per harness rules)
__device__ float    g_G[NN * DD];          // normalized hard_neg directions
__device__ float    g_HP[NN * DD];         // hard_pos vectors
__device__ float    g_HPN[NN];             // hard_pos norms (clamped)
__device__ float    g_S[(size_t)NN * NN];  // cosine sim matrix (Mn part), 64MB
__device__ float    g_SI[NN];              // per-row si
__device__ float    g_LOSS[NN];            // per-pair loss
__device__ unsigned g_MPB[NN * NN / 32];   // Mp bitmask

__device__ __forceinline__ bool mp_bit(unsigned idx) {
    return (g_MPB[idx >> 5] >> (idx & 31u)) & 1u;
}

// ---------------------------------------------------------------- k_zero
__global__ void k_zero(float* out) {
    unsigned i = blockIdx.x * blockDim.x + threadIdx.x;
    unsigned n = NN * NN / 32;
    for (; i < n; i += gridDim.x * blockDim.x) g_MPB[i] = 0u;
    if (blockIdx.x == 0 && threadIdx.x == 0) out[0] = 0.0f;
}

// ---------------------------------------------------------------- k_pairprep
// One block (128 threads) per pair: set Mp bit, compute hard_pos row + norm.
__global__ void k_pairprep(const float* __restrict__ emb, const int* __restrict__ pp) {
    int m = blockIdx.x;
    int a = pp[2 * m], b = pp[2 * m + 1];
    int t = threadIdx.x;
    if (t == 0) {
        unsigned bi = (unsigned)a * NN + (unsigned)b;
        atomicOr(&g_MPB[bi >> 5], 1u << (bi & 31u));
    }
    float v = 1.5f * emb[a * DD + t] - 0.5f * emb[b * DD + t];
    g_HP[a * DD + t] = v;
    float s = v * v;
    #pragma unroll
    for (int o = 16; o; o >>= 1) s += __shfl_xor_sync(0xffffffffu, s, o);
    __shared__ float sb[4];
    if ((t & 31) == 0) sb[t >> 5] = s;
    __syncthreads();
    if (t == 0) {
        float tot = sb[0] + sb[1] + sb[2] + sb[3];
        g_HPN[a] = fmaxf(sqrtf(tot), EPSV);
    }
}

// ---------------------------------------------------------------- k_rowprep
// One block (128 threads) per row: partner via argmax logic, normalized g.
__global__ void k_rowprep(const float* __restrict__ emb) {
    int r = blockIdx.x;
    int t = threadIdx.x;
    __shared__ int sp;
    __shared__ float nrm_s;
    if (t == 0) {
        int imax = -1;
        for (int i = NN - 1; i >= 0; --i)
            if (i != r && !mp_bit((unsigned)i * NN + (unsigned)r)) { imax = i; break; }
        int jmax = -1;
        for (int j = NN - 1; j >= 0; --j)
            if (j != r && !mp_bit((unsigned)r * NN + (unsigned)j)) { jmax = j; break; }
        long long cm = (long long)imax * NN + r;
        long long rm = (long long)r * NN + jmax;
        sp = (cm > rm) ? imax : jmax;
    }
    __syncthreads();
    int p = sp;
    float hv = 0.5f * (emb[r * DD + t] + emb[p * DD + t]);
    float s = hv * hv;
    #pragma unroll
    for (int o = 16; o; o >>= 1) s += __shfl_xor_sync(0xffffffffu, s, o);
    __shared__ float sb[4];
    if ((t & 31) == 0) sb[t >> 5] = s;
    __syncthreads();
    if (t == 0) nrm_s = fmaxf(sqrtf(sb[0] + sb[1] + sb[2] + sb[3]), EPSV);
    __syncthreads();
    g_G[r * DD + t] = hv / nrm_s;
}

// ---------------------------------------------------------------- k_gemm
// S = G * G^T, 128x128 tile per CTA, 256 threads, 8x8 micro-tile, K=128 in 4 steps.
#define BM 128
#define BK 32
__global__ void __launch_bounds__(256) k_gemm() {
    __shared__ float As[BK][BM + 4];
    __shared__ float Bs[BK][BM + 4];
    int i0 = blockIdx.y * BM;
    int j0 = blockIdx.x * BM;
    int tid = threadIdx.x;
    int tm = tid >> 4;     // 0..15
    int tn = tid & 15;     // 0..15

    float acc[8][8];
    #pragma unroll
    for (int i = 0; i < 8; i++)
        #pragma unroll
        for (int j = 0; j < 8; j++) acc[i][j] = 0.0f;

    for (int k0 = 0; k0 < DD; k0 += BK) {
        #pragma unroll
        for (int q = 0; q < 4; q++) {
            int idx = q * 256 + tid;
            int row = idx >> 3;
            int kv  = idx & 7;
            float4 va = *(const float4*)&g_G[(size_t)(i0 + row) * DD + k0 + kv * 4];
            As[kv * 4 + 0][row] = va.x; As[kv * 4 + 1][row] = va.y;
            As[kv * 4 + 2][row] = va.z; As[kv * 4 + 3][row] = va.w;
            float4 vb = *(const float4*)&g_G[(size_t)(j0 + row) * DD + k0 + kv * 4];
            Bs[kv * 4 + 0][row] = vb.x; Bs[kv * 4 + 1][row] = vb.y;
            Bs[kv * 4 + 2][row] = vb.z; Bs[kv * 4 + 3][row] = vb.w;
        }
        __syncthreads();
        #pragma unroll
        for (int kk = 0; kk < BK; kk++) {
            float a[8], b[8];
            *(float4*)&a[0] = *(float4*)&As[kk][tm * 8];
            *(float4*)&a[4] = *(float4*)&As[kk][tm * 8 + 4];
            *(float4*)&b[0] = *(float4*)&Bs[kk][tn * 8];
            *(float4*)&b[4] = *(float4*)&Bs[kk][tn * 8 + 4];
            #pragma unroll
            for (int i = 0; i < 8; i++)
                #pragma unroll
                for (int j = 0; j < 8; j++)
                    acc[i][j] = fmaf(a[i], b[j], acc[i][j]);
        }
        __syncthreads();
    }
    #pragma unroll
    for (int i = 0; i < 8; i++) {
        float* dst = &g_S[(size_t)(i0 + tm * 8 + i) * NN + j0 + tn * 8];
        *(float4*)&dst[0] = make_float4(acc[i][0], acc[i][1], acc[i][2], acc[i][3]);
        *(float4*)&dst[4] = make_float4(acc[i][4], acc[i][5], acc[i][6], acc[i][7]);
    }
}

// ---------------------------------------------------------------- k_select
__device__ __forceinline__ float blockReduceSum256(float v, float* buf) {
    int lane = threadIdx.x & 31, wid = threadIdx.x >> 5;
    #pragma unroll
    for (int o = 16; o; o >>= 1) v += __shfl_xor_sync(0xffffffffu, v, o);
    __syncthreads();
    if (lane == 0) buf[wid] = v;
    __syncthreads();
    if (threadIdx.x == 0) {
        float t = 0.0f;
        #pragma unroll
        for (int w = 0; w < 8; w++) t += buf[w];
        buf[0] = t;
    }
    __syncthreads();
    return buf[0];
}

__global__ void __launch_bounds__(256) k_select(const int* __restrict__ stage) {
    int r = blockIdx.x;
    int tid = threadIdx.x;
    __shared__ float    sv[NN];
    __shared__ unsigned hist[NBINS];
    __shared__ unsigned csum[256];
    __shared__ unsigned suf[257];
    __shared__ float    blist[LCAP];
    __shared__ unsigned lcnt;
    __shared__ int      bstar_s;
    __shared__ unsigned cab_s;
    __shared__ float    thr_s;
    __shared__ float    redf[256];
    __shared__ int      redi[256];

    const float* Srow = &g_S[(size_t)r * NN];
    for (int j = tid; j < NN; j += 256) {
        float v = Srow[j];
        bool masked = (j == r) || mp_bit((unsigned)r * NN + (unsigned)j);
        sv[j] = masked ? -2.0f : v;
    }
    for (int b = tid; b < NBINS; b += 256) hist[b] = 0u;
    if (tid == 0) lcnt = 0u;
    __syncthreads();

    if (stage[0] == 0) {  // no quantile: sum all valid
        float loc = 0.0f;
        for (int j = tid; j < NN; j += 256) {
            float v = sv[j];
            if (v > -1.5f) loc += expf(v * TAU_INV);
        }
        float tot = blockReduceSum256(loc, redf);
        if (tid == 0) g_SI[r] = tot;
        return;
    }

    // histogram over cos in [-1, 1]
    for (int j = tid; j < NN; j += 256) {
        float v = sv[j];
        if (v > -1.5f) {
            int b = (int)((v + 1.0f) * (NBINS * 0.5f));
            b = min(max(b, 0), NBINS - 1);
            atomicAdd(&hist[b], 1u);
        }
    }
    __syncthreads();

    // suffix counts -> threshold bin b* = max b with C(b) >= TOPK
    csum[tid] = hist[4 * tid] + hist[4 * tid + 1] + hist[4 * tid + 2] + hist[4 * tid + 3];
    __syncthreads();
    if (tid == 0) {
        unsigned acc = 0;
        suf[256] = 0;
        for (int t2 = 255; t2 >= 0; --t2) { acc += csum[t2]; suf[t2] = acc; }
    }
    __syncthreads();
    {
        unsigned acc = suf[tid + 1];
        #pragma unroll
        for (int u = 3; u >= 0; --u) {
            int b = 4 * tid + u;
            unsigned cb = acc + hist[b];
            if (cb >= (unsigned)TOPK && acc < (unsigned)TOPK) { bstar_s = b; cab_s = acc; }
            acc = cb;
        }
    }
    __syncthreads();
    int bstar = bstar_s;
    unsigned need = (unsigned)TOPK - cab_s;

    // collect threshold-bin elements
    for (int j = tid; j < NN; j += 256) {
        float v = sv[j];
        if (v > -1.5f) {
            int b = (int)((v + 1.0f) * (NBINS * 0.5f));
            b = min(max(b, 0), NBINS - 1);
            if (b == bstar) {
                unsigned idx = atomicAdd(&lcnt, 1u);
                if (idx < LCAP) blist[idx] = v;
            }
        }
    }
    __syncthreads();
    int cnt = (int)min(lcnt, (unsigned)LCAP);

    // need-th largest within the bin -> exact threshold value
    for (unsigned it = 0; it < need; ++it) {
        float lv = -1e30f; int li = -1;
        for (int x = tid; x < cnt; x += 256) {
            float v = blist[x];
            if (v > lv) { lv = v; li = x; }
        }
        redf[tid] = lv; redi[tid] = li;
        __syncthreads();
        #pragma unroll
        for (int o = 128; o; o >>= 1) {
            if (tid < o) {
                if (redf[tid + o] > redf[tid]) { redf[tid] = redf[tid + o]; redi[tid] = redi[tid + o]; }
            }
            __syncthreads();
        }
        if (tid == 0) { thr_s = redf[0]; blist[redi[0]] = -1e30f; }
        __syncthreads();
    }
    float thr = thr_s;

    // si = sum of exp over all v >= thr (exact tie semantics of ei >= ti)
    float loc = 0.0f;
    for (int j = tid; j < NN; j += 256) {
        float v = sv[j];
        if (v > -1.5f && v >= thr) loc += expf(v * TAU_INV);
    }
    float tot = blockReduceSum256(loc, redf);
    if (tid == 0) g_SI[r] = tot;
}

// ---------------------------------------------------------------- k_pairloss
__global__ void k_pairloss(const int* __restrict__ pp) {
    int m = blockIdx.x;
    int a = pp[2 * m], b = pp[2 * m + 1];
    int t = threadIdx.x;
    float s = g_HP[a * DD + t] * g_HP[b * DD + t];
    #pragma unroll
    for (int o = 16; o; o >>= 1) s += __shfl_xor_sync(0xffffffffu, s, o);
    __shared__ float sb[4];
    if ((t & 31) == 0) sb[t >> 5] = s;
    __syncthreads();
    if (t == 0) {
        float dot = sb[0] + sb[1] + sb[2] + sb[3];
        float c = dot / (g_HPN[a] * g_HPN[b]);
        float p = expf(c * TAU_INV);
        g_LOSS[m] = logf((p + g_SI[a]) / p) + logf((p + g_SI[b]) / p);
    }
}

// ---------------------------------------------------------------- k_final
__global__ void k_final(float* out, int npairs) {
    __shared__ float sb[1024];
    int tid = threadIdx.x;
    float s = 0.0f;
    for (int m = tid; m < npairs; m += 1024) s += g_LOSS[m];
    sb[tid] = s;
    __syncthreads();
    for (int o = 512; o; o >>= 1) {
        if (tid < o) sb[tid] += sb[tid + o];
        __syncthreads();
    }
    if (tid == 0) out[0] = sb[0] / (2.0f * (float)npairs);
}

// ---------------------------------------------------------------- launch
extern "C" void kernel_launch(void* const* d_in, const int* in_sizes, int n_in,
                              void* d_out, int out_size) {
    const float* emb   = (const float*)d_in[0];
    const int*   pp    = (const int*)d_in[1];
    const int*   stage = (const int*)d_in[2];
    int npairs = in_sizes[1] / 2;
    float* out = (float*)d_out;

    k_zero<<<2048, 256>>>(out);
    k_pairprep<<<npairs, 128>>>(emb, pp);
    k_rowprep<<<NN, 128>>>(emb);
    dim3 g(NN / BM, NN / BM);
    k_gemm<<<g, 256>>>();
    k_select<<<NN, 256>>>(stage);
    k_pairloss<<<npairs, 128>>>(pp);
    k_final<<<1, 1024>>>(out, npairs);
}

// round 4
// speedup vs baseline: 1.0009x; 1.0009x over previous
#include <cuda_runtime.h>
#include <math.h>

#define NN 4096
#define DD 128
#define TAU_INV 5.0f
#define EPSV 1e-8f
#define QIDX 3276              // floor(0.8 * (NN-1))
#define TOPK (NN - QIDX)       // 820
#define NBINS 1024
#define LCAP 1024

// Scratch (static __device__ arrays, per harness rules)
__device__ float    g_G[NN * DD];          // normalized hard_neg directions
__device__ float    g_HP[NN * DD];         // hard_pos vectors
__device__ float    g_HPN[NN];             // hard_pos norms (clamped)
__device__ float    g_S[(size_t)NN * NN];  // cosine sim matrix (Mn part), 64MB
__device__ float    g_SI[NN];              // per-row si
__device__ float    g_LOSS[NN];            // per-pair loss
__device__ unsigned g_MPB[NN * NN / 32];   // Mp bitmask

__device__ __forceinline__ bool mp_bit(unsigned idx) {
    return (g_MPB[idx >> 5] >> (idx & 31u)) & 1u;
}

// ---------------------------------------------------------------- k_zero
__global__ void k_zero(float* out) {
    unsigned i = blockIdx.x * blockDim.x + threadIdx.x;
    unsigned n = NN * NN / 32;
    for (; i < n; i += gridDim.x * blockDim.x) g_MPB[i] = 0u;
    if (blockIdx.x == 0 && threadIdx.x == 0) out[0] = 0.0f;
}

// ---------------------------------------------------------------- k_pairprep
// One block (128 threads) per pair: set Mp bit, compute hard_pos row + norm.
__global__ void k_pairprep(const float* __restrict__ emb, const int* __restrict__ pp) {
    int m = blockIdx.x;
    int a = pp[2 * m], b = pp[2 * m + 1];
    int t = threadIdx.x;
    if (t == 0) {
        unsigned bi = (unsigned)a * NN + (unsigned)b;
        atomicOr(&g_MPB[bi >> 5], 1u << (bi & 31u));
    }
    float v = 1.5f * emb[a * DD + t] - 0.5f * emb[b * DD + t];
    g_HP[a * DD + t] = v;
    float s = v * v;
    #pragma unroll
    for (int o = 16; o; o >>= 1) s += __shfl_xor_sync(0xffffffffu, s, o);
    __shared__ float sb[4];
    if ((t & 31) == 0) sb[t >> 5] = s;
    __syncthreads();
    if (t == 0) {
        float tot = sb[0] + sb[1] + sb[2] + sb[3];
        g_HPN[a] = fmaxf(sqrtf(tot), EPSV);
    }
}

// ---------------------------------------------------------------- k_rowprep
// One block (128 threads) per row: partner via argmax logic, normalized g.
__global__ void k_rowprep(const float* __restrict__ emb) {
    int r = blockIdx.x;
    int t = threadIdx.x;
    __shared__ int sp;
    __shared__ float nrm_s;
    if (t == 0) {
        int imax = -1;
        for (int i = NN - 1; i >= 0; --i)
            if (i != r && !mp_bit((unsigned)i * NN + (unsigned)r)) { imax = i; break; }
        int jmax = -1;
        for (int j = NN - 1; j >= 0; --j)
            if (j != r && !mp_bit((unsigned)r * NN + (unsigned)j)) { jmax = j; break; }
        long long cm = (long long)imax * NN + r;
        long long rm = (long long)r * NN + jmax;
        sp = (cm > rm) ? imax : jmax;
    }
    __syncthreads();
    int p = sp;
    float hv = 0.5f * (emb[r * DD + t] + emb[p * DD + t]);
    float s = hv * hv;
    #pragma unroll
    for (int o = 16; o; o >>= 1) s += __shfl_xor_sync(0xffffffffu, s, o);
    __shared__ float sb[4];
    if ((t & 31) == 0) sb[t >> 5] = s;
    __syncthreads();
    if (t == 0) nrm_s = fmaxf(sqrtf(sb[0] + sb[1] + sb[2] + sb[3]), EPSV);
    __syncthreads();
    g_G[r * DD + t] = hv / nrm_s;
}

// ---------------------------------------------------------------- k_gemm
// S = G * G^T, 128x128 tile per CTA, 256 threads, 8x8 micro-tile, K=128 in 4 steps.
#define BM 128
#define BK 32
__global__ void __launch_bounds__(256) k_gemm() {
    __shared__ float As[BK][BM + 4];
    __shared__ float Bs[BK][BM + 4];
    int i0 = blockIdx.y * BM;
    int j0 = blockIdx.x * BM;
    int tid = threadIdx.x;
    int tm = tid >> 4;     // 0..15
    int tn = tid & 15;     // 0..15

    float acc[8][8];
    #pragma unroll
    for (int i = 0; i < 8; i++)
        #pragma unroll
        for (int j = 0; j < 8; j++) acc[i][j] = 0.0f;

    for (int k0 = 0; k0 < DD; k0 += BK) {
        #pragma unroll
        for (int q = 0; q < 4; q++) {
            int idx = q * 256 + tid;
            int row = idx >> 3;
            int kv  = idx & 7;
            float4 va = *(const float4*)&g_G[(size_t)(i0 + row) * DD + k0 + kv * 4];
            As[kv * 4 + 0][row] = va.x; As[kv * 4 + 1][row] = va.y;
            As[kv * 4 + 2][row] = va.z; As[kv * 4 + 3][row] = va.w;
            float4 vb = *(const float4*)&g_G[(size_t)(j0 + row) * DD + k0 + kv * 4];
            Bs[kv * 4 + 0][row] = vb.x; Bs[kv * 4 + 1][row] = vb.y;
            Bs[kv * 4 + 2][row] = vb.z; Bs[kv * 4 + 3][row] = vb.w;
        }
        __syncthreads();
        #pragma unroll
        for (int kk = 0; kk < BK; kk++) {
            float a[8], b[8];
            *(float4*)&a[0] = *(float4*)&As[kk][tm * 8];
            *(float4*)&a[4] = *(float4*)&As[kk][tm * 8 + 4];
            *(float4*)&b[0] = *(float4*)&Bs[kk][tn * 8];
            *(float4*)&b[4] = *(float4*)&Bs[kk][tn * 8 + 4];
            #pragma unroll
            for (int i = 0; i < 8; i++)
                #pragma unroll
                for (int j = 0; j < 8; j++)
                    acc[i][j] = fmaf(a[i], b[j], acc[i][j]);
        }
        __syncthreads();
    }
    #pragma unroll
    for (int i = 0; i < 8; i++) {
        float* dst = &g_S[(size_t)(i0 + tm * 8 + i) * NN + j0 + tn * 8];
        *(float4*)&dst[0] = make_float4(acc[i][0], acc[i][1], acc[i][2], acc[i][3]);
        *(float4*)&dst[4] = make_float4(acc[i][4], acc[i][5], acc[i][6], acc[i][7]);
    }
}

// ---------------------------------------------------------------- k_select
__device__ __forceinline__ float blockReduceSum256(float v, float* buf) {
    int lane = threadIdx.x & 31, wid = threadIdx.x >> 5;
    #pragma unroll
    for (int o = 16; o; o >>= 1) v += __shfl_xor_sync(0xffffffffu, v, o);
    __syncthreads();
    if (lane == 0) buf[wid] = v;
    __syncthreads();
    if (threadIdx.x == 0) {
        float t = 0.0f;
        #pragma unroll
        for (int w = 0; w < 8; w++) t += buf[w];
        buf[0] = t;
    }
    __syncthreads();
    return buf[0];
}

__global__ void __launch_bounds__(256) k_select(const int* __restrict__ stage) {
    int r = blockIdx.x;
    int tid = threadIdx.x;
    __shared__ float    sv[NN];
    __shared__ unsigned hist[NBINS];
    __shared__ unsigned csum[256];
    __shared__ unsigned suf[257];
    __shared__ float    blist[LCAP];
    __shared__ unsigned lcnt;
    __shared__ int      bstar_s;
    __shared__ unsigned cab_s;
    __shared__ float    thr_s;
    __shared__ float    redf[256];
    __shared__ int      redi[256];

    const float* Srow = &g_S[(size_t)r * NN];
    for (int j = tid; j < NN; j += 256) {
        float v = Srow[j];
        bool masked = (j == r) || mp_bit((unsigned)r * NN + (unsigned)j);
        sv[j] = masked ? -2.0f : v;
    }
    for (int b = tid; b < NBINS; b += 256) hist[b] = 0u;
    if (tid == 0) lcnt = 0u;
    __syncthreads();

    if (stage[0] == 0) {  // no quantile: sum all valid
        float loc = 0.0f;
        for (int j = tid; j < NN; j += 256) {
            float v = sv[j];
            if (v > -1.5f) loc += expf(v * TAU_INV);
        }
        float tot = blockReduceSum256(loc, redf);
        if (tid == 0) g_SI[r] = tot;
        return;
    }

    // histogram over cos in [-1, 1]
    for (int j = tid; j < NN; j += 256) {
        float v = sv[j];
        if (v > -1.5f) {
            int b = (int)((v + 1.0f) * (NBINS * 0.5f));
            b = min(max(b, 0), NBINS - 1);
            atomicAdd(&hist[b], 1u);
        }
    }
    __syncthreads();

    // suffix counts -> threshold bin b* = max b with C(b) >= TOPK
    csum[tid] = hist[4 * tid] + hist[4 * tid + 1] + hist[4 * tid + 2] + hist[4 * tid + 3];
    __syncthreads();
    if (tid == 0) {
        unsigned acc = 0;
        suf[256] = 0;
        for (int t2 = 255; t2 >= 0; --t2) { acc += csum[t2]; suf[t2] = acc; }
    }
    __syncthreads();
    {
        unsigned acc = suf[tid + 1];
        #pragma unroll
        for (int u = 3; u >= 0; --u) {
            int b = 4 * tid + u;
            unsigned cb = acc + hist[b];
            if (cb >= (unsigned)TOPK && acc < (unsigned)TOPK) { bstar_s = b; cab_s = acc; }
            acc = cb;
        }
    }
    __syncthreads();
    int bstar = bstar_s;
    unsigned need = (unsigned)TOPK - cab_s;

    // collect threshold-bin elements
    for (int j = tid; j < NN; j += 256) {
        float v = sv[j];
        if (v > -1.5f) {
            int b = (int)((v + 1.0f) * (NBINS * 0.5f));
            b = min(max(b, 0), NBINS - 1);
            if (b == bstar) {
                unsigned idx = atomicAdd(&lcnt, 1u);
                if (idx < LCAP) blist[idx] = v;
            }
        }
    }
    __syncthreads();
    int cnt = (int)min(lcnt, (unsigned)LCAP);

    // need-th largest within the bin -> exact threshold value
    for (unsigned it = 0; it < need; ++it) {
        float lv = -1e30f; int li = -1;
        for (int x = tid; x < cnt; x += 256) {
            float v = blist[x];
            if (v > lv) { lv = v; li = x; }
        }
        redf[tid] = lv; redi[tid] = li;
        __syncthreads();
        #pragma unroll
        for (int o = 128; o; o >>= 1) {
            if (tid < o) {
                if (redf[tid + o] > redf[tid]) { redf[tid] = redf[tid + o]; redi[tid] = redi[tid + o]; }
            }
            __syncthreads();
        }
        if (tid == 0) { thr_s = redf[0]; blist[redi[0]] = -1e30f; }
        __syncthreads();
    }
    float thr = thr_s;

    // si = sum of exp over all v >= thr (exact tie semantics of ei >= ti)
    float loc = 0.0f;
    for (int j = tid; j < NN; j += 256) {
        float v = sv[j];
        if (v > -1.5f && v >= thr) loc += expf(v * TAU_INV);
    }
    float tot = blockReduceSum256(loc, redf);
    if (tid == 0) g_SI[r] = tot;
}

// ---------------------------------------------------------------- k_pairloss
__global__ void k_pairloss(const int* __restrict__ pp) {
    int m = blockIdx.x;
    int a = pp[2 * m], b = pp[2 * m + 1];
    int t = threadIdx.x;
    float s = g_HP[a * DD + t] * g_HP[b * DD + t];
    #pragma unroll
    for (int o = 16; o; o >>= 1) s += __shfl_xor_sync(0xffffffffu, s, o);
    __shared__ float sb[4];
    if ((t & 31) == 0) sb[t >> 5] = s;
    __syncthreads();
    if (t == 0) {
        float dot = sb[0] + sb[1] + sb[2] + sb[3];
        float c = dot / (g_HPN[a] * g_HPN[b]);
        float p = expf(c * TAU_INV);
        g_LOSS[m] = logf((p + g_SI[a]) / p) + logf((p + g_SI[b]) / p);
    }
}

// ---------------------------------------------------------------- k_final
__global__ void k_final(float* out, int npairs) {
    __shared__ float sb[1024];
    int tid = threadIdx.x;
    float s = 0.0f;
    for (int m = tid; m < npairs; m += 1024) s += g_LOSS[m];
    sb[tid] = s;
    __syncthreads();
    for (int o = 512; o; o >>= 1) {
        if (tid < o) sb[tid] += sb[tid + o];
        __syncthreads();
    }
    if (tid == 0) out[0] = sb[0] / (2.0f * (float)npairs);
}

// ---------------------------------------------------------------- launch
extern "C" void kernel_launch(void* const* d_in, const int* in_sizes, int n_in,
                              void* d_out, int out_size) {
    const float* emb   = (const float*)d_in[0];
    const int*   pp    = (const int*)d_in[1];
    const int*   stage = (const int*)d_in[2];
    int npairs = in_sizes[1] / 2;
    float* out = (float*)d_out;

    k_zero<<<2048, 256>>>(out);
    k_pairprep<<<npairs, 128>>>(emb, pp);
    k_rowprep<<<NN, 128>>>(emb);
    dim3 g(NN / BM, NN / BM);
    k_gemm<<<g, 256>>>();
    k_select<<<NN, 256>>>(stage);
    k_pairloss<<<npairs, 128>>>(pp);
    k_final<<<1, 1024>>>(out, npairs);
}